// round 1
// baseline (speedup 1.0000x reference)
#include <cuda_runtime.h>
#include <cuda_bf16.h>

#define N_NODES 100000
#define F_IN 256
#define F_OUT 16

// Scratch (static __device__ — no allocation allowed)
__device__ __align__(16) float g_deg[N_NODES];
__device__ __align__(16) float g_hn1[N_NODES * F_OUT];   // (x@W1) * deg_isqrt[n]
__device__ __align__(16) float g_agg1[N_NODES * F_OUT];  // edge-aggregated, init = hn1 (self loop)
__device__ __align__(16) float g_hn2[N_NODES];           // layer-2 scaled scalar
__device__ __align__(16) float g_agg2[N_NODES];

// ---------------------------------------------------------------------------
// K0: deg init (self-loop contributes 1)
__global__ void k_deg_init() {
    int n = blockIdx.x * blockDim.x + threadIdx.x;
    if (n < N_NODES) g_deg[n] = 1.0f;
}

// K1: deg accumulate over edges (dst side, matches reference)
__global__ void k_deg_edges(const int* __restrict__ dst, int E) {
    int e = blockIdx.x * blockDim.x + threadIdx.x;
    if (e < E) atomicAdd(&g_deg[dst[e]], 1.0f);
}

// ---------------------------------------------------------------------------
// K2: GEMM1 + fold deg_isqrt[n]:  hn1[n][f] = (sum_k x[n][k]*W1[k][f]) * rsqrt(deg[n])
// 16 nodes per 256-thread block. x tile staged transposed in smem (pad 17 to
// kill bank conflicts), W1 staged once.
#define NPB 16
__global__ __launch_bounds__(256) void k_gemm1(const float* __restrict__ x,
                                               const float* __restrict__ W1) {
    __shared__ float sW[F_IN * F_OUT];       // 16 KB, W1[k*16+f]
    __shared__ float sXT[F_IN * 17];         // transposed x tile, stride 17

    int tid = threadIdx.x;
    int n0 = blockIdx.x * NPB;

    // load W1 (coalesced)
    #pragma unroll
    for (int i = tid; i < F_IN * F_OUT; i += 256) sW[i] = W1[i];

    // load x tile transposed: 16 nodes x 256 feats (coalesced global reads)
    const float* xb = x + (size_t)n0 * F_IN;
    #pragma unroll
    for (int i = tid; i < NPB * F_IN; i += 256) {
        int n = i >> 8;          // i / 256
        int k = i & 255;
        sXT[k * 17 + n] = xb[i];
    }
    __syncthreads();

    int n = tid >> 4;            // 0..15
    int f = tid & 15;            // 0..15
    float acc = 0.0f;
    #pragma unroll 8
    for (int k = 0; k < F_IN; k++)
        acc = fmaf(sXT[k * 17 + n], sW[k * F_OUT + f], acc);

    int node = n0 + n;
    float v = acc * rsqrtf(g_deg[node]);
    g_hn1[node * F_OUT + f] = v;
    g_agg1[node * F_OUT + f] = v;    // self-loop init
}

// ---------------------------------------------------------------------------
// K3: edge aggregation layer 1: agg1[dst] += hn1[src]  (16 floats via 4x red.v4)
__global__ void k_edge1(const int* __restrict__ src, const int* __restrict__ dst, int E) {
    int e = blockIdx.x * blockDim.x + threadIdx.x;
    if (e >= E) return;
    int s = src[e];
    int d = dst[e];
    const float4* hs = (const float4*)(g_hn1 + (size_t)s * F_OUT);
    float* ad = g_agg1 + (size_t)d * F_OUT;
    #pragma unroll
    for (int c = 0; c < 4; c++) {
        float4 v = __ldg(hs + c);
        asm volatile("red.global.add.v4.f32 [%0], {%1, %2, %3, %4};"
                     :: "l"(ad + c * 4), "f"(v.x), "f"(v.y), "f"(v.z), "f"(v.w)
                     : "memory");
    }
}

// ---------------------------------------------------------------------------
// K4: node epilogue L1 + GEMM2 (16->1) + fold scale:
//   o1[f] = relu(isq*agg1[n][f] + b1[f]);  hn2[n] = (sum_f o1[f]*W2[f]) * isq
__global__ void k_node2(const float* __restrict__ b1, const float* __restrict__ W2) {
    int n = blockIdx.x * blockDim.x + threadIdx.x;
    if (n >= N_NODES) return;
    float isq = rsqrtf(g_deg[n]);
    const float4* ar = (const float4*)(g_agg1 + (size_t)n * F_OUT);
    float h2 = 0.0f;
    #pragma unroll
    for (int c = 0; c < 4; c++) {
        float4 a = ar[c];
        float v;
        v = fmaxf(fmaf(isq, a.x, __ldg(b1 + c * 4 + 0)), 0.0f); h2 = fmaf(v, __ldg(W2 + c * 4 + 0), h2);
        v = fmaxf(fmaf(isq, a.y, __ldg(b1 + c * 4 + 1)), 0.0f); h2 = fmaf(v, __ldg(W2 + c * 4 + 1), h2);
        v = fmaxf(fmaf(isq, a.z, __ldg(b1 + c * 4 + 2)), 0.0f); h2 = fmaf(v, __ldg(W2 + c * 4 + 2), h2);
        v = fmaxf(fmaf(isq, a.w, __ldg(b1 + c * 4 + 3)), 0.0f); h2 = fmaf(v, __ldg(W2 + c * 4 + 3), h2);
    }
    float v2 = h2 * isq;
    g_hn2[n] = v2;
    g_agg2[n] = v2;                  // self-loop init
}

// ---------------------------------------------------------------------------
// K5: edge aggregation layer 2 (scalar)
__global__ void k_edge2(const int* __restrict__ src, const int* __restrict__ dst, int E) {
    int e = blockIdx.x * blockDim.x + threadIdx.x;
    if (e >= E) return;
    atomicAdd(&g_agg2[dst[e]], g_hn2[src[e]]);
}

// K6: final output: out[n] = isq*agg2[n] + b2
__global__ void k_final(float* __restrict__ out, const float* __restrict__ b2) {
    int n = blockIdx.x * blockDim.x + threadIdx.x;
    if (n >= N_NODES) return;
    out[n] = fmaf(rsqrtf(g_deg[n]), g_agg2[n], __ldg(b2));
}

// ---------------------------------------------------------------------------
extern "C" void kernel_launch(void* const* d_in, const int* in_sizes, int n_in,
                              void* d_out, int out_size) {
    const float* x  = (const float*)d_in[0];
    const int*   ei = (const int*)d_in[1];
    const float* W1 = (const float*)d_in[2];
    const float* b1 = (const float*)d_in[3];
    const float* W2 = (const float*)d_in[4];
    const float* b2 = (const float*)d_in[5];
    float* out = (float*)d_out;

    int E = in_sizes[1] / 2;
    const int* src = ei;
    const int* dst = ei + E;

    int nb_nodes = (N_NODES + 255) / 256;
    int nb_edges = (E + 255) / 256;

    k_deg_init<<<nb_nodes, 256>>>();
    k_deg_edges<<<nb_edges, 256>>>(dst, E);
    k_gemm1<<<N_NODES / NPB, 256>>>(x, W1);
    k_edge1<<<nb_edges, 256>>>(src, dst, E);
    k_node2<<<nb_nodes, 256>>>(b1, W2);
    k_edge2<<<nb_edges, 256>>>(src, dst, E);
    k_final<<<nb_nodes, 256>>>(out, b2);
}

// round 2
// speedup vs baseline: 1.2814x; 1.2814x over previous
#include <cuda_runtime.h>
#include <cuda_bf16.h>

#define N_NODES 100000
#define F_IN 256
#define F_OUT 16

// Scratch (static __device__ — no allocation allowed)
__device__ __align__(16) float g_deg[N_NODES];
__device__ __align__(16) float g_hn1[N_NODES * F_OUT];   // (x@W1) * deg_isqrt[n]
__device__ __align__(16) float g_agg1[N_NODES * F_OUT];  // edge-aggregated, init = hn1 (self loop)
__device__ __align__(16) float g_hn2[N_NODES];           // layer-2 scaled scalar
__device__ __align__(16) float g_agg2[N_NODES];

// ---------------------------------------------------------------------------
// K0: deg init (self-loop contributes 1)
__global__ void k_deg_init() {
    int n = blockIdx.x * blockDim.x + threadIdx.x;
    if (n < N_NODES) g_deg[n] = 1.0f;
}

// K1: deg accumulate over edges (dst side) — 4 edges per thread via int4
__global__ void k_deg_edges(const int* __restrict__ dst, int E) {
    int t = blockIdx.x * blockDim.x + threadIdx.x;
    int e0 = t * 4;
    if (e0 + 3 < E) {
        int4 d = __ldg((const int4*)(dst + e0));
        atomicAdd(&g_deg[d.x], 1.0f);
        atomicAdd(&g_deg[d.y], 1.0f);
        atomicAdd(&g_deg[d.z], 1.0f);
        atomicAdd(&g_deg[d.w], 1.0f);
    } else {
        for (int e = e0; e < E; e++) atomicAdd(&g_deg[dst[e]], 1.0f);
    }
}

// ---------------------------------------------------------------------------
// K2: GEMM1 + fold deg_isqrt:  hn1[n][f] = (sum_k x[n][k]*W1[k][f]) * rsqrt(deg[n])
// 256 threads = 64 nodes x 4 f-quads. x streamed from GMEM (LDG.128, deduped
// 4-way within warp), W1 staged in smem (broadcast LDS.128). 4 independent
// accumulators per thread -> FMA-pipe bound, not LDS bound.
__global__ __launch_bounds__(256) void k_gemm1(const float* __restrict__ x,
                                               const float* __restrict__ W1) {
    __shared__ float sW[F_IN * F_OUT];   // 16 KB, sW[k*16+f]
    int tid = threadIdx.x;
    #pragma unroll
    for (int i = tid; i < F_IN * F_OUT; i += 256) sW[i] = W1[i];
    __syncthreads();

    int nl = tid >> 2;                    // 0..63
    int fq = tid & 3;                     // 0..3
    int node = blockIdx.x * 64 + nl;
    if (node >= N_NODES) return;

    const float4* xr = (const float4*)(x + (size_t)node * F_IN);
    const float4* wq = (const float4*)(sW + fq * 4);   // advance by 4 float4 per k

    float4 acc = make_float4(0.f, 0.f, 0.f, 0.f);
    #pragma unroll 8
    for (int k4 = 0; k4 < F_IN / 4; k4++) {
        float4 xv = __ldg(xr + k4);
        float4 w0 = wq[(k4 * 4 + 0) * 4];
        float4 w1 = wq[(k4 * 4 + 1) * 4];
        float4 w2 = wq[(k4 * 4 + 2) * 4];
        float4 w3 = wq[(k4 * 4 + 3) * 4];
        acc.x = fmaf(xv.x, w0.x, acc.x); acc.y = fmaf(xv.x, w0.y, acc.y);
        acc.z = fmaf(xv.x, w0.z, acc.z); acc.w = fmaf(xv.x, w0.w, acc.w);
        acc.x = fmaf(xv.y, w1.x, acc.x); acc.y = fmaf(xv.y, w1.y, acc.y);
        acc.z = fmaf(xv.y, w1.z, acc.z); acc.w = fmaf(xv.y, w1.w, acc.w);
        acc.x = fmaf(xv.z, w2.x, acc.x); acc.y = fmaf(xv.z, w2.y, acc.y);
        acc.z = fmaf(xv.z, w2.z, acc.z); acc.w = fmaf(xv.z, w2.w, acc.w);
        acc.x = fmaf(xv.w, w3.x, acc.x); acc.y = fmaf(xv.w, w3.y, acc.y);
        acc.z = fmaf(xv.w, w3.z, acc.z); acc.w = fmaf(xv.w, w3.w, acc.w);
    }

    float isq = rsqrtf(g_deg[node]);
    acc.x *= isq; acc.y *= isq; acc.z *= isq; acc.w *= isq;
    float4* h = (float4*)(g_hn1 + (size_t)node * F_OUT) + fq;
    float4* a = (float4*)(g_agg1 + (size_t)node * F_OUT) + fq;
    *h = acc;
    *a = acc;    // self-loop init
}

// ---------------------------------------------------------------------------
// K3: edge aggregation layer 1: agg1[dst] += hn1[src]
// 4 lanes per edge: each lane moves one float4 -> contiguous 64B gather per
// 4-lane group (vs 32 scattered rows per LDG before).
__global__ void k_edge1(const int* __restrict__ src, const int* __restrict__ dst,
                        int E) {
    int t = blockIdx.x * blockDim.x + threadIdx.x;
    int e = t >> 2;
    int c = t & 3;
    if (e >= E) return;
    int s = __ldg(src + e);
    int d = __ldg(dst + e);
    float4 v = __ldg((const float4*)(g_hn1 + (size_t)s * F_OUT) + c);
    float* ad = g_agg1 + (size_t)d * F_OUT + c * 4;
    asm volatile("red.global.add.v4.f32 [%0], {%1, %2, %3, %4};"
                 :: "l"(ad), "f"(v.x), "f"(v.y), "f"(v.z), "f"(v.w)
                 : "memory");
}

// ---------------------------------------------------------------------------
// K4: node epilogue L1 + GEMM2 (16->1) + fold scale
__global__ void k_node2(const float* __restrict__ b1, const float* __restrict__ W2) {
    int n = blockIdx.x * blockDim.x + threadIdx.x;
    if (n >= N_NODES) return;
    float isq = rsqrtf(g_deg[n]);
    const float4* ar = (const float4*)(g_agg1 + (size_t)n * F_OUT);
    float h2 = 0.0f;
    #pragma unroll
    for (int c = 0; c < 4; c++) {
        float4 a = ar[c];
        float v;
        v = fmaxf(fmaf(isq, a.x, __ldg(b1 + c * 4 + 0)), 0.0f); h2 = fmaf(v, __ldg(W2 + c * 4 + 0), h2);
        v = fmaxf(fmaf(isq, a.y, __ldg(b1 + c * 4 + 1)), 0.0f); h2 = fmaf(v, __ldg(W2 + c * 4 + 1), h2);
        v = fmaxf(fmaf(isq, a.z, __ldg(b1 + c * 4 + 2)), 0.0f); h2 = fmaf(v, __ldg(W2 + c * 4 + 2), h2);
        v = fmaxf(fmaf(isq, a.w, __ldg(b1 + c * 4 + 3)), 0.0f); h2 = fmaf(v, __ldg(W2 + c * 4 + 3), h2);
    }
    float v2 = h2 * isq;
    g_hn2[n] = v2;
    g_agg2[n] = v2;                  // self-loop init
}

// ---------------------------------------------------------------------------
// K5: edge aggregation layer 2 (scalar)
__global__ void k_edge2(const int* __restrict__ src, const int* __restrict__ dst, int E) {
    int e = blockIdx.x * blockDim.x + threadIdx.x;
    if (e >= E) return;
    atomicAdd(&g_agg2[dst[e]], g_hn2[src[e]]);
}

// K6: final output: out[n] = isq*agg2[n] + b2
__global__ void k_final(float* __restrict__ out, const float* __restrict__ b2) {
    int n = blockIdx.x * blockDim.x + threadIdx.x;
    if (n >= N_NODES) return;
    out[n] = fmaf(rsqrtf(g_deg[n]), g_agg2[n], __ldg(b2));
}

// ---------------------------------------------------------------------------
extern "C" void kernel_launch(void* const* d_in, const int* in_sizes, int n_in,
                              void* d_out, int out_size) {
    const float* x  = (const float*)d_in[0];
    const int*   ei = (const int*)d_in[1];
    const float* W1 = (const float*)d_in[2];
    const float* b1 = (const float*)d_in[3];
    const float* W2 = (const float*)d_in[4];
    const float* b2 = (const float*)d_in[5];
    float* out = (float*)d_out;

    int E = in_sizes[1] / 2;
    const int* src = ei;
    const int* dst = ei + E;

    int nb_nodes   = (N_NODES + 255) / 256;
    int nb_edges   = (E + 255) / 256;
    int nb_edges4  = ((E + 3) / 4 + 255) / 256;          // 4 edges/thread
    int nb_edge1   = ((E * 4) + 255) / 256;              // 4 threads/edge
    int nb_gemm    = (N_NODES + 63) / 64;

    k_deg_init<<<nb_nodes, 256>>>();
    k_deg_edges<<<nb_edges4, 256>>>(dst, E);
    k_gemm1<<<nb_gemm, 256>>>(x, W1);
    k_edge1<<<nb_edge1, 256>>>(src, dst, E);
    k_node2<<<nb_nodes, 256>>>(b1, W2);
    k_edge2<<<nb_edges, 256>>>(src, dst, E);
    k_final<<<nb_nodes, 256>>>(out, b2);
}

// round 3
// speedup vs baseline: 1.4353x; 1.1201x over previous
#include <cuda_runtime.h>
#include <cuda_bf16.h>

#define N_NODES 100000
#define F_IN 256
#define F_OUT 16

typedef unsigned long long ull;

// Scratch (static __device__ — no allocation allowed)
__device__ __align__(16) float g_deg[N_NODES];
__device__ __align__(16) float g_hn1[N_NODES * F_OUT];
__device__ __align__(16) float g_agg1[N_NODES * F_OUT];
__device__ __align__(16) float g_hn2[N_NODES];
__device__ __align__(16) float g_agg2[N_NODES];

#define FFMA2(d, a, b) asm("fma.rn.f32x2 %0, %1, %2, %0;" : "+l"(d) : "l"(a), "l"(b))

// ---------------------------------------------------------------------------
// K0: deg init (self-loop contributes 1)
__global__ void k_deg_init() {
    int n = blockIdx.x * blockDim.x + threadIdx.x;
    if (n < N_NODES) g_deg[n] = 1.0f;
}

// K1: deg accumulate (dst side) — 4 edges/thread via int4
__global__ void k_deg_edges_v4(const int* __restrict__ dst, int E4) {
    int t = blockIdx.x * blockDim.x + threadIdx.x;
    if (t >= E4) return;
    int4 d = __ldg((const int4*)dst + t);
    atomicAdd(&g_deg[d.x], 1.0f);
    atomicAdd(&g_deg[d.y], 1.0f);
    atomicAdd(&g_deg[d.z], 1.0f);
    atomicAdd(&g_deg[d.w], 1.0f);
}
__global__ void k_deg_edges_s(const int* __restrict__ dst, int E) {
    int e = blockIdx.x * blockDim.x + threadIdx.x;
    if (e < E) atomicAdd(&g_deg[dst[e]], 1.0f);
}

// ---------------------------------------------------------------------------
// K2: GEMM1 + fold deg_isqrt: hn1[n][f] = (x@W1)[n][f] * rsqrt(deg[n])
// 256 threads / 256 nodes per block. x staged in smem transposed (32-k chunks,
// coalesced GMEM reads), W duplicated as (w,w) float2 pairs. Per-thread tile:
// 4 nodes x 4 f, accumulated in packed f32x2 (8 FFMA2 per k).
#define KC 32
#define XSTR 258            // 8B-aligned rows (258*4 % 8 == 0), 2-way STS conflict max
#define NPB 256
#define GEMM_SMEM (KC * XSTR * 4 + F_IN * F_OUT * 8)

__global__ __launch_bounds__(256, 3) void k_gemm1(const float* __restrict__ x,
                                                  const float* __restrict__ W1) {
    extern __shared__ float smem[];
    float*  sX  = smem;                          // [KC][XSTR]
    float2* sWd = (float2*)(smem + KC * XSTR);   // [F_IN][F_OUT] duplicated pairs

    int tid = threadIdx.x;
    int n0 = blockIdx.x * NPB;

    for (int i = tid; i < F_IN * F_OUT; i += 256) {
        float w = W1[i];
        sWd[i] = make_float2(w, w);
    }

    int nq = tid >> 2;      // 0..63 -> nodes nq*4 .. nq*4+3
    int fq = tid & 3;       // f-quad

    ull acc[4][2];
    #pragma unroll
    for (int f = 0; f < 4; f++) { acc[f][0] = 0ull; acc[f][1] = 0ull; }

    for (int kc = 0; kc < F_IN; kc += KC) {
        __syncthreads();
        // stage x chunk transposed: sX[k][n] = x[n0+n][kc+k]
        #pragma unroll
        for (int j = 0; j < (NPB * KC / 4) / 256; j++) {   // 8 iters
            int i = tid + j * 256;
            int n = i >> 3;
            int kq = i & 7;
            int row = n0 + n; if (row >= N_NODES) row = N_NODES - 1;
            float4 v = __ldg((const float4*)(x + (size_t)row * F_IN + kc) + kq);
            sX[(kq * 4 + 0) * XSTR + n] = v.x;
            sX[(kq * 4 + 1) * XSTR + n] = v.y;
            sX[(kq * 4 + 2) * XSTR + n] = v.z;
            sX[(kq * 4 + 3) * XSTR + n] = v.w;
        }
        __syncthreads();
        #pragma unroll 8
        for (int k = 0; k < KC; k++) {
            const float* xp = sX + k * XSTR + nq * 4;
            ull xa = *(const ull*)xp;          // nodes 0,1 of quad
            ull xb = *(const ull*)(xp + 2);    // nodes 2,3
            const ulonglong2* wp = (const ulonglong2*)(sWd + (kc + k) * F_OUT + fq * 4);
            ulonglong2 w01 = wp[0];            // (f0,f0),(f1,f1)
            ulonglong2 w23 = wp[1];            // (f2,f2),(f3,f3)
            FFMA2(acc[0][0], xa, w01.x); FFMA2(acc[0][1], xb, w01.x);
            FFMA2(acc[1][0], xa, w01.y); FFMA2(acc[1][1], xb, w01.y);
            FFMA2(acc[2][0], xa, w23.x); FFMA2(acc[2][1], xb, w23.x);
            FFMA2(acc[3][0], xa, w23.y); FFMA2(acc[3][1], xb, w23.y);
        }
    }

    #pragma unroll
    for (int j = 0; j < 4; j++) {
        int node = n0 + nq * 4 + j;
        if (node >= N_NODES) break;
        int p = j >> 1, hi = j & 1;
        union { ull u; float2 f; } c0, c1, c2, c3;
        c0.u = acc[0][p]; c1.u = acc[1][p]; c2.u = acc[2][p]; c3.u = acc[3][p];
        float4 o;
        o.x = hi ? c0.f.y : c0.f.x;
        o.y = hi ? c1.f.y : c1.f.x;
        o.z = hi ? c2.f.y : c2.f.x;
        o.w = hi ? c3.f.y : c3.f.x;
        float isq = rsqrtf(g_deg[node]);
        o.x *= isq; o.y *= isq; o.z *= isq; o.w *= isq;
        *((float4*)(g_hn1 + (size_t)node * F_OUT) + fq) = o;
        *((float4*)(g_agg1 + (size_t)node * F_OUT) + fq) = o;   // self-loop init
    }
}

// ---------------------------------------------------------------------------
// K3: edge aggregation layer 1: agg1[dst] += hn1[src], 4 lanes per edge
__global__ void k_edge1(const int* __restrict__ src, const int* __restrict__ dst,
                        int E) {
    int t = blockIdx.x * blockDim.x + threadIdx.x;
    int e = t >> 2;
    int c = t & 3;
    if (e >= E) return;
    int s = __ldg(src + e);
    int d = __ldg(dst + e);
    float4 v = __ldg((const float4*)(g_hn1 + (size_t)s * F_OUT) + c);
    float* ad = g_agg1 + (size_t)d * F_OUT + c * 4;
    asm volatile("red.global.add.v4.f32 [%0], {%1, %2, %3, %4};"
                 :: "l"(ad), "f"(v.x), "f"(v.y), "f"(v.z), "f"(v.w)
                 : "memory");
}

// ---------------------------------------------------------------------------
// K4: node epilogue L1 + GEMM2 (16->1) + fold scale
__global__ void k_node2(const float* __restrict__ b1, const float* __restrict__ W2) {
    int n = blockIdx.x * blockDim.x + threadIdx.x;
    if (n >= N_NODES) return;
    float isq = rsqrtf(g_deg[n]);
    const float4* ar = (const float4*)(g_agg1 + (size_t)n * F_OUT);
    float h2 = 0.0f;
    #pragma unroll
    for (int c = 0; c < 4; c++) {
        float4 a = ar[c];
        float v;
        v = fmaxf(fmaf(isq, a.x, __ldg(b1 + c * 4 + 0)), 0.0f); h2 = fmaf(v, __ldg(W2 + c * 4 + 0), h2);
        v = fmaxf(fmaf(isq, a.y, __ldg(b1 + c * 4 + 1)), 0.0f); h2 = fmaf(v, __ldg(W2 + c * 4 + 1), h2);
        v = fmaxf(fmaf(isq, a.z, __ldg(b1 + c * 4 + 2)), 0.0f); h2 = fmaf(v, __ldg(W2 + c * 4 + 2), h2);
        v = fmaxf(fmaf(isq, a.w, __ldg(b1 + c * 4 + 3)), 0.0f); h2 = fmaf(v, __ldg(W2 + c * 4 + 3), h2);
    }
    float v2 = h2 * isq;
    g_hn2[n] = v2;
    g_agg2[n] = v2;                  // self-loop init
}

// ---------------------------------------------------------------------------
// K5: edge aggregation layer 2 (scalar), 4 edges/thread
__global__ void k_edge2_v4(const int* __restrict__ src, const int* __restrict__ dst,
                           int E4) {
    int t = blockIdx.x * blockDim.x + threadIdx.x;
    if (t >= E4) return;
    int4 s = __ldg((const int4*)src + t);
    int4 d = __ldg((const int4*)dst + t);
    atomicAdd(&g_agg2[d.x], __ldg(g_hn2 + s.x));
    atomicAdd(&g_agg2[d.y], __ldg(g_hn2 + s.y));
    atomicAdd(&g_agg2[d.z], __ldg(g_hn2 + s.z));
    atomicAdd(&g_agg2[d.w], __ldg(g_hn2 + s.w));
}
__global__ void k_edge2_s(const int* __restrict__ src, const int* __restrict__ dst,
                          int E) {
    int e = blockIdx.x * blockDim.x + threadIdx.x;
    if (e >= E) return;
    atomicAdd(&g_agg2[dst[e]], g_hn2[src[e]]);
}

// K6: final output
__global__ void k_final(float* __restrict__ out, const float* __restrict__ b2) {
    int n = blockIdx.x * blockDim.x + threadIdx.x;
    if (n >= N_NODES) return;
    out[n] = fmaf(rsqrtf(g_deg[n]), g_agg2[n], __ldg(b2));
}

// ---------------------------------------------------------------------------
extern "C" void kernel_launch(void* const* d_in, const int* in_sizes, int n_in,
                              void* d_out, int out_size) {
    const float* x  = (const float*)d_in[0];
    const int*   ei = (const int*)d_in[1];
    const float* W1 = (const float*)d_in[2];
    const float* b1 = (const float*)d_in[3];
    const float* W2 = (const float*)d_in[4];
    const float* b2 = (const float*)d_in[5];
    float* out = (float*)d_out;

    int E = in_sizes[1] / 2;
    const int* src = ei;
    const int* dst = ei + E;

    int nb_nodes = (N_NODES + 255) / 256;
    int nb_edge1 = ((E * 4) + 255) / 256;
    int nb_gemm  = (N_NODES + NPB - 1) / NPB;

    static bool smem_set = false;   // idempotent attribute set (not a work guard)
    cudaFuncSetAttribute(k_gemm1, cudaFuncAttributeMaxDynamicSharedMemorySize,
                         GEMM_SMEM);

    k_deg_init<<<nb_nodes, 256>>>();
    if ((E & 3) == 0) {
        int E4 = E / 4;
        int nb4 = (E4 + 255) / 256;
        k_deg_edges_v4<<<nb4, 256>>>(dst, E4);
        k_gemm1<<<nb_gemm, 256, GEMM_SMEM>>>(x, W1);
        k_edge1<<<nb_edge1, 256>>>(src, dst, E);
        k_node2<<<nb_nodes, 256>>>(b1, W2);
        k_edge2_v4<<<nb4, 256>>>(src, dst, E4);
    } else {
        int nb = (E + 255) / 256;
        k_deg_edges_s<<<nb, 256>>>(dst, E);
        k_gemm1<<<nb_gemm, 256, GEMM_SMEM>>>(x, W1);
        k_edge1<<<nb_edge1, 256>>>(src, dst, E);
        k_node2<<<nb_nodes, 256>>>(b1, W2);
        k_edge2_s<<<nb, 256>>>(src, dst, E);
    }
    k_final<<<nb_nodes, 256>>>(out, b2);
    (void)smem_set;
}

// round 4
// speedup vs baseline: 1.4383x; 1.0021x over previous
#include <cuda_runtime.h>
#include <cuda_bf16.h>
#include <cuda_fp16.h>

#define N_NODES 100000
#define F_IN 256
#define F_OUT 16

typedef unsigned long long ull;

// Scratch (static __device__ — no allocation allowed)
__device__ __align__(16) float  g_deg[N_NODES];
__device__ __align__(16) __half g_hn1h[N_NODES * F_OUT];   // fp16 messages, layer 1
__device__ __align__(16) float  g_agg1[N_NODES * F_OUT];   // fp32 accum, init = self-loop
__device__ __align__(16) float  g_hn2[N_NODES];
__device__ __align__(16) float  g_agg2[N_NODES];

#define FFMA2(d, a, b) asm("fma.rn.f32x2 %0, %1, %2, %0;" : "+l"(d) : "l"(a), "l"(b))

// ---------------------------------------------------------------------------
// K0: deg init (self-loop contributes 1)
__global__ void k_deg_init() {
    int n = blockIdx.x * blockDim.x + threadIdx.x;
    if (n < N_NODES) g_deg[n] = 1.0f;
}

// K1: deg accumulate (dst side) — 4 edges/thread via int4
__global__ void k_deg_edges_v4(const int* __restrict__ dst, int E4) {
    int t = blockIdx.x * blockDim.x + threadIdx.x;
    if (t >= E4) return;
    int4 d = __ldg((const int4*)dst + t);
    atomicAdd(&g_deg[d.x], 1.0f);
    atomicAdd(&g_deg[d.y], 1.0f);
    atomicAdd(&g_deg[d.z], 1.0f);
    atomicAdd(&g_deg[d.w], 1.0f);
}
__global__ void k_deg_edges_s(const int* __restrict__ dst, int E) {
    int e = blockIdx.x * blockDim.x + threadIdx.x;
    if (e < E) atomicAdd(&g_deg[dst[e]], 1.0f);
}

// ---------------------------------------------------------------------------
// K2: GEMM1 + fold deg_isqrt. Writes fp32 agg1 (self-loop init) + fp16 hn1h.
#define KC 32
#define XSTR 258
#define NPB 256
#define GEMM_SMEM (KC * XSTR * 4 + F_IN * F_OUT * 8)

__global__ __launch_bounds__(256, 3) void k_gemm1(const float* __restrict__ x,
                                                  const float* __restrict__ W1) {
    extern __shared__ float smem[];
    float*  sX  = smem;                          // [KC][XSTR]
    float2* sWd = (float2*)(smem + KC * XSTR);   // [F_IN][F_OUT] duplicated pairs

    int tid = threadIdx.x;
    int n0 = blockIdx.x * NPB;

    for (int i = tid; i < F_IN * F_OUT; i += 256) {
        float w = W1[i];
        sWd[i] = make_float2(w, w);
    }

    int nq = tid >> 2;      // 0..63
    int fq = tid & 3;       // 0..3

    ull acc[4][2];
    #pragma unroll
    for (int f = 0; f < 4; f++) { acc[f][0] = 0ull; acc[f][1] = 0ull; }

    for (int kc = 0; kc < F_IN; kc += KC) {
        __syncthreads();
        #pragma unroll
        for (int j = 0; j < (NPB * KC / 4) / 256; j++) {   // 8 iters
            int i = tid + j * 256;
            int n = i >> 3;
            int kq = i & 7;
            int row = n0 + n; if (row >= N_NODES) row = N_NODES - 1;
            float4 v = __ldg((const float4*)(x + (size_t)row * F_IN + kc) + kq);
            sX[(kq * 4 + 0) * XSTR + n] = v.x;
            sX[(kq * 4 + 1) * XSTR + n] = v.y;
            sX[(kq * 4 + 2) * XSTR + n] = v.z;
            sX[(kq * 4 + 3) * XSTR + n] = v.w;
        }
        __syncthreads();
        #pragma unroll 8
        for (int k = 0; k < KC; k++) {
            const float* xp = sX + k * XSTR + nq * 4;
            ull xa = *(const ull*)xp;
            ull xb = *(const ull*)(xp + 2);
            const ulonglong2* wp = (const ulonglong2*)(sWd + (kc + k) * F_OUT + fq * 4);
            ulonglong2 w01 = wp[0];
            ulonglong2 w23 = wp[1];
            FFMA2(acc[0][0], xa, w01.x); FFMA2(acc[0][1], xb, w01.x);
            FFMA2(acc[1][0], xa, w01.y); FFMA2(acc[1][1], xb, w01.y);
            FFMA2(acc[2][0], xa, w23.x); FFMA2(acc[2][1], xb, w23.x);
            FFMA2(acc[3][0], xa, w23.y); FFMA2(acc[3][1], xb, w23.y);
        }
    }

    #pragma unroll
    for (int j = 0; j < 4; j++) {
        int node = n0 + nq * 4 + j;
        if (node >= N_NODES) break;
        int p = j >> 1, hi = j & 1;
        union { ull u; float2 f; } c0, c1, c2, c3;
        c0.u = acc[0][p]; c1.u = acc[1][p]; c2.u = acc[2][p]; c3.u = acc[3][p];
        float4 o;
        o.x = hi ? c0.f.y : c0.f.x;
        o.y = hi ? c1.f.y : c1.f.x;
        o.z = hi ? c2.f.y : c2.f.x;
        o.w = hi ? c3.f.y : c3.f.x;
        float isq = rsqrtf(g_deg[node]);
        o.x *= isq; o.y *= isq; o.z *= isq; o.w *= isq;
        *((float4*)(g_agg1 + (size_t)node * F_OUT) + fq) = o;    // self-loop init (exact fp32)
        __half2 ha = __floats2half2_rn(o.x, o.y);
        __half2 hb = __floats2half2_rn(o.z, o.w);
        __half2* hp = (__half2*)(g_hn1h + (size_t)node * F_OUT + fq * 4);
        hp[0] = ha;
        hp[1] = hb;
    }
}

// ---------------------------------------------------------------------------
// K3: edge aggregation layer 1: agg1[dst] += fp16(hn1h[src]), 2 lanes/edge.
// Each lane: one LDG.128 fetches 8 fp16 feats, convert, 2x red.v4.f32.
__global__ void k_edge1(const int* __restrict__ src, const int* __restrict__ dst,
                        int E) {
    int t = blockIdx.x * blockDim.x + threadIdx.x;
    int e = t >> 1;
    int h = t & 1;
    if (e >= E) return;
    int s = __ldg(src + e);
    int d = __ldg(dst + e);
    const uint4* hp = (const uint4*)(g_hn1h + (size_t)s * F_OUT + h * 8);
    uint4 raw = __ldg(hp);
    float2 f0 = __half22float2(*(const __half2*)&raw.x);
    float2 f1 = __half22float2(*(const __half2*)&raw.y);
    float2 f2 = __half22float2(*(const __half2*)&raw.z);
    float2 f3 = __half22float2(*(const __half2*)&raw.w);
    float* ad = g_agg1 + (size_t)d * F_OUT + h * 8;
    asm volatile("red.global.add.v4.f32 [%0], {%1, %2, %3, %4};"
                 :: "l"(ad), "f"(f0.x), "f"(f0.y), "f"(f1.x), "f"(f1.y)
                 : "memory");
    asm volatile("red.global.add.v4.f32 [%0], {%1, %2, %3, %4};"
                 :: "l"(ad + 4), "f"(f2.x), "f"(f2.y), "f"(f3.x), "f"(f3.y)
                 : "memory");
}

// ---------------------------------------------------------------------------
// K4: node epilogue L1 + GEMM2 (16->1) + fold scale
__global__ void k_node2(const float* __restrict__ b1, const float* __restrict__ W2) {
    int n = blockIdx.x * blockDim.x + threadIdx.x;
    if (n >= N_NODES) return;
    float isq = rsqrtf(g_deg[n]);
    const float4* ar = (const float4*)(g_agg1 + (size_t)n * F_OUT);
    float h2 = 0.0f;
    #pragma unroll
    for (int c = 0; c < 4; c++) {
        float4 a = ar[c];
        float v;
        v = fmaxf(fmaf(isq, a.x, __ldg(b1 + c * 4 + 0)), 0.0f); h2 = fmaf(v, __ldg(W2 + c * 4 + 0), h2);
        v = fmaxf(fmaf(isq, a.y, __ldg(b1 + c * 4 + 1)), 0.0f); h2 = fmaf(v, __ldg(W2 + c * 4 + 1), h2);
        v = fmaxf(fmaf(isq, a.z, __ldg(b1 + c * 4 + 2)), 0.0f); h2 = fmaf(v, __ldg(W2 + c * 4 + 2), h2);
        v = fmaxf(fmaf(isq, a.w, __ldg(b1 + c * 4 + 3)), 0.0f); h2 = fmaf(v, __ldg(W2 + c * 4 + 3), h2);
    }
    float v2 = h2 * isq;
    g_hn2[n] = v2;
    g_agg2[n] = v2;                  // self-loop init
}

// ---------------------------------------------------------------------------
// K5: edge aggregation layer 2 (scalar), 4 edges/thread
__global__ void k_edge2_v4(const int* __restrict__ src, const int* __restrict__ dst,
                           int E4) {
    int t = blockIdx.x * blockDim.x + threadIdx.x;
    if (t >= E4) return;
    int4 s = __ldg((const int4*)src + t);
    int4 d = __ldg((const int4*)dst + t);
    atomicAdd(&g_agg2[d.x], __ldg(g_hn2 + s.x));
    atomicAdd(&g_agg2[d.y], __ldg(g_hn2 + s.y));
    atomicAdd(&g_agg2[d.z], __ldg(g_hn2 + s.z));
    atomicAdd(&g_agg2[d.w], __ldg(g_hn2 + s.w));
}
__global__ void k_edge2_s(const int* __restrict__ src, const int* __restrict__ dst,
                          int E) {
    int e = blockIdx.x * blockDim.x + threadIdx.x;
    if (e >= E) return;
    atomicAdd(&g_agg2[dst[e]], g_hn2[src[e]]);
}

// K6: final output
__global__ void k_final(float* __restrict__ out, const float* __restrict__ b2) {
    int n = blockIdx.x * blockDim.x + threadIdx.x;
    if (n >= N_NODES) return;
    out[n] = fmaf(rsqrtf(g_deg[n]), g_agg2[n], __ldg(b2));
}

// ---------------------------------------------------------------------------
extern "C" void kernel_launch(void* const* d_in, const int* in_sizes, int n_in,
                              void* d_out, int out_size) {
    const float* x  = (const float*)d_in[0];
    const int*   ei = (const int*)d_in[1];
    const float* W1 = (const float*)d_in[2];
    const float* b1 = (const float*)d_in[3];
    const float* W2 = (const float*)d_in[4];
    const float* b2 = (const float*)d_in[5];
    float* out = (float*)d_out;

    int E = in_sizes[1] / 2;
    const int* src = ei;
    const int* dst = ei + E;

    int nb_nodes = (N_NODES + 255) / 256;
    int nb_edge1 = ((E * 2) + 255) / 256;     // 2 lanes/edge
    int nb_gemm  = (N_NODES + NPB - 1) / NPB;

    cudaFuncSetAttribute(k_gemm1, cudaFuncAttributeMaxDynamicSharedMemorySize,
                         GEMM_SMEM);

    k_deg_init<<<nb_nodes, 256>>>();
    if ((E & 3) == 0) {
        int E4 = E / 4;
        int nb4 = (E4 + 255) / 256;
        k_deg_edges_v4<<<nb4, 256>>>(dst, E4);
        k_gemm1<<<nb_gemm, 256, GEMM_SMEM>>>(x, W1);
        k_edge1<<<nb_edge1, 256>>>(src, dst, E);
        k_node2<<<nb_nodes, 256>>>(b1, W2);
        k_edge2_v4<<<nb4, 256>>>(src, dst, E4);
    } else {
        int nb = (E + 255) / 256;
        k_deg_edges_s<<<nb, 256>>>(dst, E);
        k_gemm1<<<nb_gemm, 256, GEMM_SMEM>>>(x, W1);
        k_edge1<<<nb_edge1, 256>>>(src, dst, E);
        k_node2<<<nb_nodes, 256>>>(b1, W2);
        k_edge2_s<<<nb, 256>>>(src, dst, E);
    }
    k_final<<<nb_nodes, 256>>>(out, b2);
}

// round 6
// speedup vs baseline: 1.5715x; 1.0926x over previous
#include <cuda_runtime.h>
#include <cuda_bf16.h>

#define N_NODES 100000
#define F_IN 256
#define F_OUT 16

typedef unsigned long long ull;

// Scratch (static __device__ — no allocation allowed)
__device__ __align__(16) float g_deg[N_NODES];
__device__ __align__(16) float g_hn1[N_NODES * F_OUT];   // raw then scaled messages
__device__ __align__(16) float g_agg1[N_NODES * F_OUT];  // fp32 accum, init = self-loop
__device__ __align__(16) float g_hn2[N_NODES];
__device__ __align__(16) float g_agg2[N_NODES];

#define FFMA2(d, a, b) asm("fma.rn.f32x2 %0, %1, %2, %0;" : "+l"(d) : "l"(a), "l"(b))

// ---------------------------------------------------------------------------
// K0: deg init (self-loop contributes 1)
__global__ void k_deg_init() {
    int n = blockIdx.x * blockDim.x + threadIdx.x;
    if (n < N_NODES) g_deg[n] = 1.0f;
}

// ---------------------------------------------------------------------------
// K1 (fused): blocks [0, nbGemm) = GEMM1 raw (hn1 = x@W1, unscaled);
//             blocks [nbGemm, ..) = degree atomics (independent of GEMM).
#define KC 32
#define XSTR 258
#define NPB 256
#define GEMM_SMEM (KC * XSTR * 4 + F_IN * F_OUT * 8)

__global__ __launch_bounds__(256, 3) void k_fused(const float* __restrict__ x,
                                                  const float* __restrict__ W1,
                                                  const int* __restrict__ dst,
                                                  int E, int nbGemm) {
    extern __shared__ float smem[];
    int tid = threadIdx.x;

    if (blockIdx.x >= nbGemm) {
        // ---- degree pass: 4 edges/thread via int4, tail on thread E4 ----
        int E4 = E >> 2;
        int t = (blockIdx.x - nbGemm) * 256 + tid;
        if (t < E4) {
            int4 d = __ldg((const int4*)dst + t);
            atomicAdd(&g_deg[d.x], 1.0f);
            atomicAdd(&g_deg[d.y], 1.0f);
            atomicAdd(&g_deg[d.z], 1.0f);
            atomicAdd(&g_deg[d.w], 1.0f);
        } else if (t == E4) {
            for (int e = E4 * 4; e < E; e++) atomicAdd(&g_deg[dst[e]], 1.0f);
        }
        return;
    }

    // ---- GEMM1 raw ----
    float*  sX  = smem;                          // [KC][XSTR]
    float2* sWd = (float2*)(smem + KC * XSTR);   // [F_IN][F_OUT] duplicated pairs

    int n0 = blockIdx.x * NPB;
    for (int i = tid; i < F_IN * F_OUT; i += 256) {
        float w = W1[i];
        sWd[i] = make_float2(w, w);
    }

    int nq = tid >> 2;      // 0..63
    int fq = tid & 3;       // 0..3

    ull acc[4][2];
    #pragma unroll
    for (int f = 0; f < 4; f++) { acc[f][0] = 0ull; acc[f][1] = 0ull; }

    for (int kc = 0; kc < F_IN; kc += KC) {
        __syncthreads();
        #pragma unroll
        for (int j = 0; j < (NPB * KC / 4) / 256; j++) {   // 8 iters
            int i = tid + j * 256;
            int n = i >> 3;
            int kq = i & 7;
            int row = n0 + n; if (row >= N_NODES) row = N_NODES - 1;
            float4 v = __ldg((const float4*)(x + (size_t)row * F_IN + kc) + kq);
            sX[(kq * 4 + 0) * XSTR + n] = v.x;
            sX[(kq * 4 + 1) * XSTR + n] = v.y;
            sX[(kq * 4 + 2) * XSTR + n] = v.z;
            sX[(kq * 4 + 3) * XSTR + n] = v.w;
        }
        __syncthreads();
        #pragma unroll 8
        for (int k = 0; k < KC; k++) {
            const float* xp = sX + k * XSTR + nq * 4;
            ull xa = *(const ull*)xp;
            ull xb = *(const ull*)(xp + 2);
            const ulonglong2* wp = (const ulonglong2*)(sWd + (kc + k) * F_OUT + fq * 4);
            ulonglong2 w01 = wp[0];
            ulonglong2 w23 = wp[1];
            FFMA2(acc[0][0], xa, w01.x); FFMA2(acc[0][1], xb, w01.x);
            FFMA2(acc[1][0], xa, w01.y); FFMA2(acc[1][1], xb, w01.y);
            FFMA2(acc[2][0], xa, w23.x); FFMA2(acc[2][1], xb, w23.x);
            FFMA2(acc[3][0], xa, w23.y); FFMA2(acc[3][1], xb, w23.y);
        }
    }

    #pragma unroll
    for (int j = 0; j < 4; j++) {
        int node = n0 + nq * 4 + j;
        if (node >= N_NODES) break;
        int p = j >> 1, hi = j & 1;
        union { ull u; float2 f; } c0, c1, c2, c3;
        c0.u = acc[0][p]; c1.u = acc[1][p]; c2.u = acc[2][p]; c3.u = acc[3][p];
        float4 o;
        o.x = hi ? c0.f.y : c0.f.x;
        o.y = hi ? c1.f.y : c1.f.x;
        o.z = hi ? c2.f.y : c2.f.x;
        o.w = hi ? c3.f.y : c3.f.x;
        *((float4*)(g_hn1 + (size_t)node * F_OUT) + fq) = o;   // raw, unscaled
    }
}

// ---------------------------------------------------------------------------
// K2: scale: hn1 *= isq (messages), agg1 = hn1*isq (self-loop init)
__global__ void k_scale() {
    int t = blockIdx.x * blockDim.x + threadIdx.x;
    int n = t >> 2;
    int fq = t & 3;
    if (n >= N_NODES) return;
    float isq = rsqrtf(g_deg[n]);
    float4* hp = (float4*)(g_hn1 + (size_t)n * F_OUT) + fq;
    float4 o = *hp;
    o.x *= isq; o.y *= isq; o.z *= isq; o.w *= isq;
    *hp = o;
    *((float4*)(g_agg1 + (size_t)n * F_OUT) + fq) = o;
}

// ---------------------------------------------------------------------------
// K3: edge aggregation layer 1: agg1[dst] += hn1[src]
// 4 lanes per edge, 2 edges per thread (independent chains -> 2x MLP).
__global__ void k_edge1(const int* __restrict__ src, const int* __restrict__ dst,
                        int E, int Eh) {
    int t = blockIdx.x * blockDim.x + threadIdx.x;
    int q = t >> 2;
    int c = t & 3;
    if (q >= Eh) return;
    int e0 = q;
    int e1 = q + Eh;
    int s0 = __ldg(src + e0);
    int d0 = __ldg(dst + e0);
    float4 v0 = __ldg((const float4*)(g_hn1 + (size_t)s0 * F_OUT) + c);
    if (e1 < E) {
        int s1 = __ldg(src + e1);
        int d1 = __ldg(dst + e1);
        float4 v1 = __ldg((const float4*)(g_hn1 + (size_t)s1 * F_OUT) + c);
        float* a0 = g_agg1 + (size_t)d0 * F_OUT + c * 4;
        float* a1 = g_agg1 + (size_t)d1 * F_OUT + c * 4;
        asm volatile("red.global.add.v4.f32 [%0], {%1, %2, %3, %4};"
                     :: "l"(a0), "f"(v0.x), "f"(v0.y), "f"(v0.z), "f"(v0.w) : "memory");
        asm volatile("red.global.add.v4.f32 [%0], {%1, %2, %3, %4};"
                     :: "l"(a1), "f"(v1.x), "f"(v1.y), "f"(v1.z), "f"(v1.w) : "memory");
    } else {
        float* a0 = g_agg1 + (size_t)d0 * F_OUT + c * 4;
        asm volatile("red.global.add.v4.f32 [%0], {%1, %2, %3, %4};"
                     :: "l"(a0), "f"(v0.x), "f"(v0.y), "f"(v0.z), "f"(v0.w) : "memory");
    }
}

// ---------------------------------------------------------------------------
// K4: node epilogue L1 + GEMM2 (16->1) + fold scale
__global__ void k_node2(const float* __restrict__ b1, const float* __restrict__ W2) {
    int n = blockIdx.x * blockDim.x + threadIdx.x;
    if (n >= N_NODES) return;
    float isq = rsqrtf(g_deg[n]);
    const float4* ar = (const float4*)(g_agg1 + (size_t)n * F_OUT);
    float h2 = 0.0f;
    #pragma unroll
    for (int c = 0; c < 4; c++) {
        float4 a = ar[c];
        float v;
        v = fmaxf(fmaf(isq, a.x, __ldg(b1 + c * 4 + 0)), 0.0f); h2 = fmaf(v, __ldg(W2 + c * 4 + 0), h2);
        v = fmaxf(fmaf(isq, a.y, __ldg(b1 + c * 4 + 1)), 0.0f); h2 = fmaf(v, __ldg(W2 + c * 4 + 1), h2);
        v = fmaxf(fmaf(isq, a.z, __ldg(b1 + c * 4 + 2)), 0.0f); h2 = fmaf(v, __ldg(W2 + c * 4 + 2), h2);
        v = fmaxf(fmaf(isq, a.w, __ldg(b1 + c * 4 + 3)), 0.0f); h2 = fmaf(v, __ldg(W2 + c * 4 + 3), h2);
    }
    float v2 = h2 * isq;
    g_hn2[n] = v2;
    g_agg2[n] = v2;                  // self-loop init
}

// ---------------------------------------------------------------------------
// K5: edge aggregation layer 2 (scalar), 4 edges/thread + tail
__global__ void k_edge2(const int* __restrict__ src, const int* __restrict__ dst,
                        int E) {
    int E4 = E >> 2;
    int t = blockIdx.x * blockDim.x + threadIdx.x;
    if (t < E4) {
        int4 s = __ldg((const int4*)src + t);
        int4 d = __ldg((const int4*)dst + t);
        atomicAdd(&g_agg2[d.x], __ldg(g_hn2 + s.x));
        atomicAdd(&g_agg2[d.y], __ldg(g_hn2 + s.y));
        atomicAdd(&g_agg2[d.z], __ldg(g_hn2 + s.z));
        atomicAdd(&g_agg2[d.w], __ldg(g_hn2 + s.w));
    } else if (t == E4) {
        for (int e = E4 * 4; e < E; e++)
            atomicAdd(&g_agg2[dst[e]], g_hn2[src[e]]);
    }
}

// K6: final output
__global__ void k_final(float* __restrict__ out, const float* __restrict__ b2) {
    int n = blockIdx.x * blockDim.x + threadIdx.x;
    if (n >= N_NODES) return;
    out[n] = fmaf(rsqrtf(g_deg[n]), g_agg2[n], __ldg(b2));
}

// ---------------------------------------------------------------------------
extern "C" void kernel_launch(void* const* d_in, const int* in_sizes, int n_in,
                              void* d_out, int out_size) {
    const float* x  = (const float*)d_in[0];
    const int*   ei = (const int*)d_in[1];
    const float* W1 = (const float*)d_in[2];
    const float* b1 = (const float*)d_in[3];
    const float* W2 = (const float*)d_in[4];
    const float* b2 = (const float*)d_in[5];
    float* out = (float*)d_out;

    int E = in_sizes[1] / 2;
    const int* src = ei;
    const int* dst = ei + E;

    int nb_nodes = (N_NODES + 255) / 256;
    int nb_gemm  = (N_NODES + NPB - 1) / NPB;
    int nb_deg   = ((E >> 2) + 1 + 255) / 256;           // int4 threads + tail thread
    int Eh       = (E + 1) >> 1;                          // 2 edges/thread in edge1
    int nb_e1    = ((Eh * 4) + 255) / 256;
    int nb_e2    = ((E >> 2) + 1 + 255) / 256;
    int nb_scale = (N_NODES * 4 + 255) / 256;

    cudaFuncSetAttribute(k_fused, cudaFuncAttributeMaxDynamicSharedMemorySize,
                         GEMM_SMEM);

    k_deg_init<<<nb_nodes, 256>>>();
    k_fused<<<nb_gemm + nb_deg, 256, GEMM_SMEM>>>(x, W1, dst, E, nb_gemm);
    k_scale<<<nb_scale, 256>>>();
    k_edge1<<<nb_e1, 256>>>(src, dst, E, Eh);
    k_node2<<<nb_nodes, 256>>>(b1, W2);
    k_edge2<<<nb_e2, 256>>>(src, dst, E);
    k_final<<<nb_nodes, 256>>>(out, b2);
}

// round 7
// speedup vs baseline: 1.6315x; 1.0382x over previous
#include <cuda_runtime.h>
#include <cuda_bf16.h>

#define N_NODES 100000
#define F_IN 256
#define F_OUT 16

typedef unsigned long long ull;

// Scratch (static __device__ — no allocation allowed)
__device__ __align__(16) float g_deg[N_NODES];
__device__ __align__(16) float g_hn1[N_NODES * F_OUT];   // raw then scaled messages
__device__ __align__(16) float g_agg1[N_NODES * F_OUT];  // fp32 accum, init = self-loop
__device__ __align__(16) float g_hn2[N_NODES];
__device__ __align__(16) float g_agg2[N_NODES];

#define FFMA2(d, a, b) asm("fma.rn.f32x2 %0, %1, %2, %0;" : "+l"(d) : "l"(a), "l"(b))
#define REDV4(p, v) asm volatile("red.global.add.v4.f32 [%0], {%1, %2, %3, %4};" \
    :: "l"(p), "f"((v).x), "f"((v).y), "f"((v).z), "f"((v).w) : "memory")

// ---------------------------------------------------------------------------
// K0: deg init (self-loop contributes 1)
__global__ void k_deg_init() {
    int n = blockIdx.x * blockDim.x + threadIdx.x;
    if (n < N_NODES) g_deg[n] = 1.0f;
}

// ---------------------------------------------------------------------------
// K1 (fused): blocks [0, nbGemm) = GEMM1 raw (hn1 = x@W1, unscaled);
//             blocks [nbGemm, ..) = degree atomics (independent of GEMM).
// 8 nodes x 4 f per thread, f32x2 packed accumulators.
#define KC 32
#define XSTR 514            // 8B-aligned ull rows, 2-way STS conflict max
#define NPB 512
#define GEMM_SMEM (KC * XSTR * 4 + F_IN * F_OUT * 8)

__global__ __launch_bounds__(256, 2) void k_fused(const float* __restrict__ x,
                                                  const float* __restrict__ W1,
                                                  const int* __restrict__ dst,
                                                  int E, int nbGemm) {
    extern __shared__ float smem[];
    int tid = threadIdx.x;

    if (blockIdx.x >= nbGemm) {
        // ---- degree pass: 4 edges/thread via int4, tail on thread E4 ----
        int E4 = E >> 2;
        int t = (blockIdx.x - nbGemm) * 256 + tid;
        if (t < E4) {
            int4 d = __ldg((const int4*)dst + t);
            atomicAdd(&g_deg[d.x], 1.0f);
            atomicAdd(&g_deg[d.y], 1.0f);
            atomicAdd(&g_deg[d.z], 1.0f);
            atomicAdd(&g_deg[d.w], 1.0f);
        } else if (t == E4) {
            for (int e = E4 * 4; e < E; e++) atomicAdd(&g_deg[dst[e]], 1.0f);
        }
        return;
    }

    // ---- GEMM1 raw ----
    float*  sX  = smem;                          // [KC][XSTR]
    float2* sWd = (float2*)(smem + KC * XSTR);   // [F_IN][F_OUT] duplicated pairs

    int n0 = blockIdx.x * NPB;
    for (int i = tid; i < F_IN * F_OUT; i += 256) {
        float w = W1[i];
        sWd[i] = make_float2(w, w);
    }

    int nq = tid >> 2;      // 0..63 -> nodes nq*8 .. nq*8+7
    int fq = tid & 3;       // 0..3

    ull acc[4][4];          // [f][node-pair]
    #pragma unroll
    for (int f = 0; f < 4; f++)
        #pragma unroll
        for (int p = 0; p < 4; p++) acc[f][p] = 0ull;

    for (int kc = 0; kc < F_IN; kc += KC) {
        __syncthreads();
        // stage x chunk transposed: sX[k][n] = x[n0+n][kc+k]; 512 nodes x 32 k
        #pragma unroll
        for (int j = 0; j < (NPB * KC / 4) / 256; j++) {   // 16 iters
            int i = tid + j * 256;
            int n = i >> 3;
            int kq = i & 7;
            int row = n0 + n; if (row >= N_NODES) row = N_NODES - 1;
            float4 v = __ldg((const float4*)(x + (size_t)row * F_IN + kc) + kq);
            sX[(kq * 4 + 0) * XSTR + n] = v.x;
            sX[(kq * 4 + 1) * XSTR + n] = v.y;
            sX[(kq * 4 + 2) * XSTR + n] = v.z;
            sX[(kq * 4 + 3) * XSTR + n] = v.w;
        }
        __syncthreads();
        #pragma unroll 4
        for (int k = 0; k < KC; k++) {
            const float* xp = sX + k * XSTR + nq * 8;
            ull xa0 = *(const ull*)xp;
            ull xa1 = *(const ull*)(xp + 2);
            ull xa2 = *(const ull*)(xp + 4);
            ull xa3 = *(const ull*)(xp + 6);
            const ulonglong2* wp = (const ulonglong2*)(sWd + (kc + k) * F_OUT + fq * 4);
            ulonglong2 w01 = wp[0];
            ulonglong2 w23 = wp[1];
            FFMA2(acc[0][0], xa0, w01.x); FFMA2(acc[0][1], xa1, w01.x);
            FFMA2(acc[0][2], xa2, w01.x); FFMA2(acc[0][3], xa3, w01.x);
            FFMA2(acc[1][0], xa0, w01.y); FFMA2(acc[1][1], xa1, w01.y);
            FFMA2(acc[1][2], xa2, w01.y); FFMA2(acc[1][3], xa3, w01.y);
            FFMA2(acc[2][0], xa0, w23.x); FFMA2(acc[2][1], xa1, w23.x);
            FFMA2(acc[2][2], xa2, w23.x); FFMA2(acc[2][3], xa3, w23.x);
            FFMA2(acc[3][0], xa0, w23.y); FFMA2(acc[3][1], xa1, w23.y);
            FFMA2(acc[3][2], xa2, w23.y); FFMA2(acc[3][3], xa3, w23.y);
        }
    }

    #pragma unroll
    for (int j = 0; j < 8; j++) {
        int node = n0 + nq * 8 + j;
        if (node >= N_NODES) break;
        int p = j >> 1, hi = j & 1;
        union { ull u; float2 f; } c0, c1, c2, c3;
        c0.u = acc[0][p]; c1.u = acc[1][p]; c2.u = acc[2][p]; c3.u = acc[3][p];
        float4 o;
        o.x = hi ? c0.f.y : c0.f.x;
        o.y = hi ? c1.f.y : c1.f.x;
        o.z = hi ? c2.f.y : c2.f.x;
        o.w = hi ? c3.f.y : c3.f.x;
        *((float4*)(g_hn1 + (size_t)node * F_OUT) + fq) = o;   // raw, unscaled
    }
}

// ---------------------------------------------------------------------------
// K2: scale: hn1 *= isq (messages), agg1 = hn1*isq (self-loop init)
__global__ void k_scale() {
    int t = blockIdx.x * blockDim.x + threadIdx.x;
    int n = t >> 2;
    int fq = t & 3;
    if (n >= N_NODES) return;
    float isq = rsqrtf(g_deg[n]);
    float4* hp = (float4*)(g_hn1 + (size_t)n * F_OUT) + fq;
    float4 o = *hp;
    o.x *= isq; o.y *= isq; o.z *= isq; o.w *= isq;
    *hp = o;
    *((float4*)(g_agg1 + (size_t)n * F_OUT) + fq) = o;
}

// ---------------------------------------------------------------------------
// K3: edge aggregation layer 1: agg1[dst] += hn1[src]
// 4 lanes per edge, 4 independent edge-chains per thread (E % 4 == 0 path).
__global__ void k_edge1_v4(const int* __restrict__ src, const int* __restrict__ dst,
                           int Eq) {
    int t = blockIdx.x * blockDim.x + threadIdx.x;
    int q = t >> 2;
    int c = t & 3;
    if (q >= Eq) return;
    int e0 = q, e1 = q + Eq, e2 = q + 2 * Eq, e3 = q + 3 * Eq;
    int s0 = __ldg(src + e0), d0 = __ldg(dst + e0);
    int s1 = __ldg(src + e1), d1 = __ldg(dst + e1);
    int s2 = __ldg(src + e2), d2 = __ldg(dst + e2);
    int s3 = __ldg(src + e3), d3 = __ldg(dst + e3);
    float4 v0 = __ldg((const float4*)(g_hn1 + (size_t)s0 * F_OUT) + c);
    float4 v1 = __ldg((const float4*)(g_hn1 + (size_t)s1 * F_OUT) + c);
    float4 v2 = __ldg((const float4*)(g_hn1 + (size_t)s2 * F_OUT) + c);
    float4 v3 = __ldg((const float4*)(g_hn1 + (size_t)s3 * F_OUT) + c);
    REDV4(g_agg1 + (size_t)d0 * F_OUT + c * 4, v0);
    REDV4(g_agg1 + (size_t)d1 * F_OUT + c * 4, v1);
    REDV4(g_agg1 + (size_t)d2 * F_OUT + c * 4, v2);
    REDV4(g_agg1 + (size_t)d3 * F_OUT + c * 4, v3);
}
// fallback: 1 edge per 4 lanes
__global__ void k_edge1_s(const int* __restrict__ src, const int* __restrict__ dst,
                          int E) {
    int t = blockIdx.x * blockDim.x + threadIdx.x;
    int e = t >> 2;
    int c = t & 3;
    if (e >= E) return;
    int s = __ldg(src + e);
    int d = __ldg(dst + e);
    float4 v = __ldg((const float4*)(g_hn1 + (size_t)s * F_OUT) + c);
    REDV4(g_agg1 + (size_t)d * F_OUT + c * 4, v);
}

// ---------------------------------------------------------------------------
// K4: node epilogue L1 + GEMM2 (16->1) + fold scale
__global__ void k_node2(const float* __restrict__ b1, const float* __restrict__ W2) {
    int n = blockIdx.x * blockDim.x + threadIdx.x;
    if (n >= N_NODES) return;
    float isq = rsqrtf(g_deg[n]);
    const float4* ar = (const float4*)(g_agg1 + (size_t)n * F_OUT);
    float h2 = 0.0f;
    #pragma unroll
    for (int c = 0; c < 4; c++) {
        float4 a = ar[c];
        float v;
        v = fmaxf(fmaf(isq, a.x, __ldg(b1 + c * 4 + 0)), 0.0f); h2 = fmaf(v, __ldg(W2 + c * 4 + 0), h2);
        v = fmaxf(fmaf(isq, a.y, __ldg(b1 + c * 4 + 1)), 0.0f); h2 = fmaf(v, __ldg(W2 + c * 4 + 1), h2);
        v = fmaxf(fmaf(isq, a.z, __ldg(b1 + c * 4 + 2)), 0.0f); h2 = fmaf(v, __ldg(W2 + c * 4 + 2), h2);
        v = fmaxf(fmaf(isq, a.w, __ldg(b1 + c * 4 + 3)), 0.0f); h2 = fmaf(v, __ldg(W2 + c * 4 + 3), h2);
    }
    float v2 = h2 * isq;
    g_hn2[n] = v2;
    g_agg2[n] = v2;                  // self-loop init
}

// ---------------------------------------------------------------------------
// K5: edge aggregation layer 2 (scalar), 8 edges/thread (2x int4) + tail
__global__ void k_edge2(const int* __restrict__ src, const int* __restrict__ dst,
                        int E) {
    int E8 = E >> 3;
    int t = blockIdx.x * blockDim.x + threadIdx.x;
    if (t < E8) {
        int4 sa = __ldg((const int4*)src + 2 * t);
        int4 sb = __ldg((const int4*)src + 2 * t + 1);
        int4 da = __ldg((const int4*)dst + 2 * t);
        int4 db = __ldg((const int4*)dst + 2 * t + 1);
        float ha = __ldg(g_hn2 + sa.x), hb = __ldg(g_hn2 + sa.y);
        float hc = __ldg(g_hn2 + sa.z), hd = __ldg(g_hn2 + sa.w);
        float he = __ldg(g_hn2 + sb.x), hf = __ldg(g_hn2 + sb.y);
        float hg = __ldg(g_hn2 + sb.z), hh = __ldg(g_hn2 + sb.w);
        atomicAdd(&g_agg2[da.x], ha);
        atomicAdd(&g_agg2[da.y], hb);
        atomicAdd(&g_agg2[da.z], hc);
        atomicAdd(&g_agg2[da.w], hd);
        atomicAdd(&g_agg2[db.x], he);
        atomicAdd(&g_agg2[db.y], hf);
        atomicAdd(&g_agg2[db.z], hg);
        atomicAdd(&g_agg2[db.w], hh);
    } else if (t == E8) {
        for (int e = E8 * 8; e < E; e++)
            atomicAdd(&g_agg2[dst[e]], g_hn2[src[e]]);
    }
}

// K6: final output
__global__ void k_final(float* __restrict__ out, const float* __restrict__ b2) {
    int n = blockIdx.x * blockDim.x + threadIdx.x;
    if (n >= N_NODES) return;
    out[n] = fmaf(rsqrtf(g_deg[n]), g_agg2[n], __ldg(b2));
}

// ---------------------------------------------------------------------------
extern "C" void kernel_launch(void* const* d_in, const int* in_sizes, int n_in,
                              void* d_out, int out_size) {
    const float* x  = (const float*)d_in[0];
    const int*   ei = (const int*)d_in[1];
    const float* W1 = (const float*)d_in[2];
    const float* b1 = (const float*)d_in[3];
    const float* W2 = (const float*)d_in[4];
    const float* b2 = (const float*)d_in[5];
    float* out = (float*)d_out;

    int E = in_sizes[1] / 2;
    const int* src = ei;
    const int* dst = ei + E;

    int nb_nodes = (N_NODES + 255) / 256;
    int nb_gemm  = (N_NODES + NPB - 1) / NPB;
    int nb_deg   = ((E >> 2) + 1 + 255) / 256;
    int nb_e2    = ((E >> 3) + 1 + 255) / 256;
    int nb_scale = (N_NODES * 4 + 255) / 256;

    cudaFuncSetAttribute(k_fused, cudaFuncAttributeMaxDynamicSharedMemorySize,
                         GEMM_SMEM);

    k_deg_init<<<nb_nodes, 256>>>();
    k_fused<<<nb_gemm + nb_deg, 256, GEMM_SMEM>>>(x, W1, dst, E, nb_gemm);
    k_scale<<<nb_scale, 256>>>();
    if ((E & 3) == 0) {
        int Eq = E >> 2;
        int nb_e1 = ((Eq * 4) + 255) / 256;
        k_edge1_v4<<<nb_e1, 256>>>(src, dst, Eq);
    } else {
        int nb_e1 = ((E * 4) + 255) / 256;
        k_edge1_s<<<nb_e1, 256>>>(src, dst, E);
    }
    k_node2<<<nb_nodes, 256>>>(b1, W2);
    k_edge2<<<nb_e2, 256>>>(src, dst, E);
    k_final<<<nb_nodes, 256>>>(out, b2);
}